// round 4
// baseline (speedup 1.0000x reference)
#include <cuda_runtime.h>
#include <cstdint>

// Problem geometry (fixed by setup_inputs: 2048 x 2048 float32).
static constexpr int H = 2048;
static constexpr int W = 2048;
static constexpr int NPIX = H * W;
static constexpr int TILE = 256;           // pixels (cols) per block, one row
static constexpr int HALO = 64;            // smem halo each side
static constexpr int WIN  = TILE + 2 * HALO;
static constexpr int NBLK = NPIX / TILE;   // 16384 blocks

// Scratch (device globals — no runtime allocation allowed).
__device__ float        g_d[NPIX];         // distance (pre-normalize)
__device__ unsigned int g_blockmax[NBLK];  // per-block max (float bits, >= 0)
__device__ unsigned int g_max_bits;        // global max (float bits)

// ---------------------------------------------------------------------------
// Exact squared column distance (full, no bound): squared distance from
// (row,col) to nearest background (img <= 0.5) along the column.
// ---------------------------------------------------------------------------
__device__ __forceinline__ float col_dist2_full(const float* __restrict__ img,
                                                int row, int col) {
    const float* p = img + col;
    if (__ldg(p + (size_t)row * W) <= 0.5f) return 0.0f;
    int up = row, down = (H - 1) - row;
    int kcap = max(up, down);
    for (int k = 1; k <= kcap; k++) {
        if (k <= up   && __ldg(p + (size_t)(row - k) * W) <= 0.5f) return (float)(k * k);
        if (k <= down && __ldg(p + (size_t)(row + k) * W) <= 0.5f) return (float)(k * k);
    }
    return 1.0e30f;                        // no background in this column
}

// Bounded variant for rare beyond-halo fallback: may return any value >= bound
// once k^2 >= bound (caller's fmin then discards it — exact).
__device__ __forceinline__ float col_dist2_bounded(const float* __restrict__ img,
                                                   int row, int col, float bound) {
    const float* p = img + col;
    if (__ldg(p + (size_t)row * W) <= 0.5f) return 0.0f;
    int up = row, down = (H - 1) - row;
    int kcap = max(up, down);
    for (int k = 1; k <= kcap; k++) {
        float fk2 = (float)(k * k);
        if (fk2 >= bound) return fk2;
        if (k <= up   && __ldg(p + (size_t)(row - k) * W) <= 0.5f) return fk2;
        if (k <= down && __ldg(p + (size_t)(row + k) * W) <= 0.5f) return fk2;
    }
    return 1.0e30f;
}

// ---------------------------------------------------------------------------
// K1: fused EDT. Block = 256 consecutive cols of one row. Cooperative smem
// window of f = colDist2 over [tile-HALO, tile+TILE+HALO), then exact outward
// row search per pixel: D = min_d f[j+d] + d^2, stop when d^2 >= best.
// ---------------------------------------------------------------------------
__global__ void k_dist(const float* __restrict__ img) {
    int row = blockIdx.x >> 3;                       // W/TILE == 8 tiles per row
    int tc0 = (blockIdx.x & 7) * TILE;

    __shared__ float sf[WIN];
#pragma unroll
    for (int i = threadIdx.x; i < WIN; i += TILE) {
        int c = tc0 - HALO + i;
        sf[i] = (c < 0 || c >= W) ? 1.0e30f : col_dist2_full(img, row, c);
    }
    __syncthreads();

    int col = tc0 + threadIdx.x;
    float best = sf[HALO + threadIdx.x];
    if (best > 0.0f) {
        int maxl = col, maxr = (W - 1) - col;
        int dmax = max(maxl, maxr);
        for (int d = 1; d <= dmax; d++) {
            float fd2 = (float)(d * d);
            if (fd2 >= best) break;                   // no farther win possible
            if (d <= HALO) {
                // out-of-row slots hold 1e30 -> fmin ignores them (exact)
                best = fminf(best, sf[HALO + threadIdx.x - d] + fd2);
                best = fminf(best, sf[HALO + threadIdx.x + d] + fd2);
            } else {                                  // rare: best > HALO^2
                if (d <= maxl)
                    best = fminf(best, col_dist2_bounded(img, row, col - d, best - fd2) + fd2);
                if (d <= maxr && fd2 < best)
                    best = fminf(best, col_dist2_bounded(img, row, col + d, best - fd2) + fd2);
            }
        }
    }
    float di = __fsqrt_rn(best);
    g_d[(size_t)row * W + col] = di;

    // block max (float bits preserve order for non-negative floats)
    unsigned int ib = __reduce_max_sync(0xffffffffu, __float_as_uint(di));
    __shared__ unsigned int sm[TILE / 32];
    if ((threadIdx.x & 31) == 0) sm[threadIdx.x >> 5] = ib;
    __syncthreads();
    if (threadIdx.x == 0) {
        unsigned int m = sm[0];
#pragma unroll
        for (int w = 1; w < TILE / 32; w++) m = max(m, sm[w]);
        g_blockmax[blockIdx.x] = m;
    }
}

// ---------------------------------------------------------------------------
// K2: single-block reduction of the 16384 block maxima.
// ---------------------------------------------------------------------------
__global__ void k_reduce() {
    unsigned int v = 0u;
    for (int i = threadIdx.x; i < NBLK; i += blockDim.x)
        v = max(v, g_blockmax[i]);
    v = __reduce_max_sync(0xffffffffu, v);
    __shared__ unsigned int sm[32];
    if ((threadIdx.x & 31) == 0) sm[threadIdx.x >> 5] = v;
    __syncthreads();
    if (threadIdx.x < 32) {
        unsigned int w = (threadIdx.x < (int)(blockDim.x >> 5)) ? sm[threadIdx.x] : 0u;
        w = __reduce_max_sync(0xffffffffu, w);
        if (threadIdx.x == 0) g_max_bits = w;
    }
}

// ---------------------------------------------------------------------------
// K3: normalize by global max, truncate toward zero (uint8 cast semantics;
// values in [0,255] so floorf). Harness exposes the output as float32.
// ---------------------------------------------------------------------------
__global__ void k_normalize(float* __restrict__ out) {
    int idx = blockIdx.x * blockDim.x + threadIdx.x;
    if (idx >= NPIX / 4) return;
    float m = __uint_as_float(g_max_bits);
    float4 v = reinterpret_cast<const float4*>(g_d)[idx];
    float4 r;
    if (m > 0.0f) {
        r.x = floorf(v.x / m * 255.0f);
        r.y = floorf(v.y / m * 255.0f);
        r.z = floorf(v.z / m * 255.0f);
        r.w = floorf(v.w / m * 255.0f);
    } else {
        r.x = floorf(v.x); r.y = floorf(v.y); r.z = floorf(v.z); r.w = floorf(v.w);
    }
    reinterpret_cast<float4*>(out)[idx] = r;
}

extern "C" void kernel_launch(void* const* d_in, const int* in_sizes, int n_in,
                              void* d_out, int out_size) {
    const float* img = (const float*)d_in[0];
    float* out = (float*)d_out;
    (void)in_sizes; (void)n_in; (void)out_size;

    k_dist<<<NBLK, TILE>>>(img);
    k_reduce<<<1, 1024>>>();
    k_normalize<<<(NPIX / 4 + 255) / 256, 256>>>(out);
}

// round 5
// speedup vs baseline: 1.3480x; 1.3480x over previous
#include <cuda_runtime.h>
#include <cstdint>

// Problem geometry (fixed by setup_inputs: 2048 x 2048 float32).
static constexpr int H = 2048;
static constexpr int W = 2048;
static constexpr int NPIX = H * W;
static constexpr int TPB = 256;
static constexpr int NBLK = NPIX / TPB;    // 16384 blocks
static constexpr float FG = 1.0e30f;       // "foreground / out of range" sentinel

// Scratch (device globals — no runtime allocation allowed).
__device__ float        g_f[NPIX];         // squared column distance
__device__ float        g_d[NPIX];         // distance (pre-normalize)
__device__ unsigned int g_blockmax[NBLK];  // per-block max (float bits, >= 0)
__device__ unsigned int g_max_bits;        // global max (float bits)

// ---------------------------------------------------------------------------
// K1: f = (distance to nearest background along the column)^2, per pixel.
// Outward probe with first two steps batched (independent loads -> MLP).
// Out-of-range probes use the FG sentinel (> 0.5 -> treated as foreground).
// Warp = 32 consecutive cols of one row -> every probe row is one 128B line.
// ---------------------------------------------------------------------------
__global__ void k_colf(const float* __restrict__ img) {
    int idx = blockIdx.x * blockDim.x + threadIdx.x;
    int row = idx >> 11;                                   // W == 2048
    const float* p = img + idx;

    float f;
    if (__ldg(p) <= 0.5f) {
        f = 0.0f;
    } else {
        int up = row, down = (H - 1) - row;
        // batched probes k = 1, 2 (4 independent loads)
        float u1 = (up   >= 1) ? __ldg(p - W)     : FG;
        float d1 = (down >= 1) ? __ldg(p + W)     : FG;
        float u2 = (up   >= 2) ? __ldg(p - 2 * W) : FG;
        float d2 = (down >= 2) ? __ldg(p + 2 * W) : FG;
        if      (u1 <= 0.5f || d1 <= 0.5f) f = 1.0f;
        else if (u2 <= 0.5f || d2 <= 0.5f) f = 4.0f;
        else {
            f = FG;
            int kcap = max(up, down);
            for (int k = 3; k <= kcap; k++) {
                float a = (k <= up)   ? __ldg(p - (size_t)k * W) : FG;
                float b = (k <= down) ? __ldg(p + (size_t)k * W) : FG;
                if (a <= 0.5f || b <= 0.5f) { f = (float)(k * k); break; }
            }
        }
    }
    g_f[idx] = f;
}

// ---------------------------------------------------------------------------
// K2: row pass. D = min_d f[j+d] + d^2 via exact outward search with bound
// d^2 >= best (valid: f >= 0). First three offsets batched (6 independent
// loads). Stores d = sqrt(D); per-block max -> g_blockmax (no atomics).
// ---------------------------------------------------------------------------
__global__ void k_row(void) {
    int idx = blockIdx.x * blockDim.x + threadIdx.x;
    int col = idx & (W - 1);
    float best = __ldg(&g_f[idx]);
    if (best > 1.0f) {
        int maxl = col, maxr = (W - 1) - col;
        // batched d = 1..3 (exact: fmin with any candidate is always valid)
        float l1 = (1 <= maxl) ? __ldg(&g_f[idx - 1]) : FG;
        float r1 = (1 <= maxr) ? __ldg(&g_f[idx + 1]) : FG;
        float l2 = (2 <= maxl) ? __ldg(&g_f[idx - 2]) : FG;
        float r2 = (2 <= maxr) ? __ldg(&g_f[idx + 2]) : FG;
        float l3 = (3 <= maxl) ? __ldg(&g_f[idx - 3]) : FG;
        float r3 = (3 <= maxr) ? __ldg(&g_f[idx + 3]) : FG;
        best = fminf(best, fminf(l1, r1) + 1.0f);
        best = fminf(best, fminf(l2, r2) + 4.0f);
        best = fminf(best, fminf(l3, r3) + 9.0f);
        for (int d = 4; d < W; d++) {
            float fd2 = (float)(d * d);
            if (fd2 >= best) break;                        // no farther win
            float lv = (d <= maxl) ? __ldg(&g_f[idx - d]) : FG;
            float rv = (d <= maxr) ? __ldg(&g_f[idx + d]) : FG;
            best = fminf(best, fminf(lv, rv) + fd2);
        }
    }
    float di = __fsqrt_rn(best);
    g_d[idx] = di;

    // block max (float bits preserve order for non-negative floats)
    unsigned int ib = __reduce_max_sync(0xffffffffu, __float_as_uint(di));
    __shared__ unsigned int sm[TPB / 32];
    if ((threadIdx.x & 31) == 0) sm[threadIdx.x >> 5] = ib;
    __syncthreads();
    if (threadIdx.x == 0) {
        unsigned int m = sm[0];
#pragma unroll
        for (int w = 1; w < TPB / 32; w++) m = max(m, sm[w]);
        g_blockmax[blockIdx.x] = m;
    }
}

// ---------------------------------------------------------------------------
// K3: single-block reduction of the 16384 block maxima.
// ---------------------------------------------------------------------------
__global__ void k_reduce() {
    unsigned int v = 0u;
    for (int i = threadIdx.x; i < NBLK; i += blockDim.x)
        v = max(v, g_blockmax[i]);
    v = __reduce_max_sync(0xffffffffu, v);
    __shared__ unsigned int sm[32];
    if ((threadIdx.x & 31) == 0) sm[threadIdx.x >> 5] = v;
    __syncthreads();
    if (threadIdx.x < 32) {
        unsigned int w = (threadIdx.x < (int)(blockDim.x >> 5)) ? sm[threadIdx.x] : 0u;
        w = __reduce_max_sync(0xffffffffu, w);
        if (threadIdx.x == 0) g_max_bits = w;
    }
}

// ---------------------------------------------------------------------------
// K4: normalize by global max, truncate toward zero (uint8 cast semantics;
// values in [0,255] so floorf). Harness exposes the output as float32.
// ---------------------------------------------------------------------------
__global__ void k_normalize(float* __restrict__ out) {
    int idx = blockIdx.x * blockDim.x + threadIdx.x;
    if (idx >= NPIX / 4) return;
    float m = __uint_as_float(g_max_bits);
    float4 v = reinterpret_cast<const float4*>(g_d)[idx];
    float4 r;
    if (m > 0.0f) {
        r.x = floorf(v.x / m * 255.0f);
        r.y = floorf(v.y / m * 255.0f);
        r.z = floorf(v.z / m * 255.0f);
        r.w = floorf(v.w / m * 255.0f);
    } else {
        r.x = floorf(v.x); r.y = floorf(v.y); r.z = floorf(v.z); r.w = floorf(v.w);
    }
    reinterpret_cast<float4*>(out)[idx] = r;
}

extern "C" void kernel_launch(void* const* d_in, const int* in_sizes, int n_in,
                              void* d_out, int out_size) {
    const float* img = (const float*)d_in[0];
    float* out = (float*)d_out;
    (void)in_sizes; (void)n_in; (void)out_size;

    k_colf<<<NBLK, TPB>>>(img);
    k_row<<<NBLK, TPB>>>();
    k_reduce<<<1, 1024>>>();
    k_normalize<<<(NPIX / 4 + 255) / 256, 256>>>(out);
}

// round 6
// speedup vs baseline: 2.0953x; 1.5544x over previous
#include <cuda_runtime.h>
#include <cstdint>

// Problem geometry (fixed by setup_inputs: 2048 x 2048 float32).
static constexpr int H = 2048;
static constexpr int W = 2048;
static constexpr int W4 = W / 4;           // float4s per row (512)
static constexpr int NPIX = H * W;
static constexpr int TPB = 256;
static constexpr int NB4 = NPIX / (TPB * 4);  // 4096 blocks (4 px / thread)
static constexpr float FG = 1.0e30f;       // "foreground / out of range" sentinel

// Scratch (device globals — no runtime allocation allowed).
__device__ float        g_f[NPIX];         // squared column distance
__device__ float        g_d[NPIX];         // distance (pre-normalize)
__device__ unsigned int g_blockmax[NB4];   // per-block max (float bits, >= 0)
__device__ unsigned int g_max_bits;        // global max (float bits)

__device__ __forceinline__ float4 fg4() { return make_float4(FG, FG, FG, FG); }

// ---------------------------------------------------------------------------
// K1: f = (distance to nearest background along the column)^2.
// One thread = 4 consecutive pixels (one aligned float4). Each probe step k
// loads two float4s (row-k, row+k) shared by all 4 lanes.
// ---------------------------------------------------------------------------
__global__ void k_colf(const float* __restrict__ img) {
    int t = blockIdx.x * blockDim.x + threadIdx.x;         // float4 index
    int row = (t << 2) >> 11;                              // W == 2048
    const float4* p = reinterpret_cast<const float4*>(img) + t;

    float4 v = __ldg(p);
    float f0 = (v.x <= 0.5f) ? 0.0f : FG;
    float f1 = (v.y <= 0.5f) ? 0.0f : FG;
    float f2 = (v.z <= 0.5f) ? 0.0f : FG;
    float f3 = (v.w <= 0.5f) ? 0.0f : FG;
    unsigned pend = (f0 != 0.0f ? 1u : 0u) | (f1 != 0.0f ? 2u : 0u) |
                    (f2 != 0.0f ? 4u : 0u) | (f3 != 0.0f ? 8u : 0u);
    if (pend) {
        int up = row, down = (H - 1) - row;
        int kcap = max(up, down);
        for (int k = 1; k <= kcap && pend; k++) {
            float4 a = (k <= up)   ? __ldg(p - (size_t)k * W4) : fg4();
            float4 b = (k <= down) ? __ldg(p + (size_t)k * W4) : fg4();
            float fk2 = (float)(k * k);
            if ((pend & 1u) && (a.x <= 0.5f || b.x <= 0.5f)) { f0 = fk2; pend &= ~1u; }
            if ((pend & 2u) && (a.y <= 0.5f || b.y <= 0.5f)) { f1 = fk2; pend &= ~2u; }
            if ((pend & 4u) && (a.z <= 0.5f || b.z <= 0.5f)) { f2 = fk2; pend &= ~4u; }
            if ((pend & 8u) && (a.w <= 0.5f || b.w <= 0.5f)) { f3 = fk2; pend &= ~8u; }
        }
    }
    reinterpret_cast<float4*>(g_f)[t] = make_float4(f0, f1, f2, f3);
}

// ---------------------------------------------------------------------------
// K2: row pass. One thread = 4 consecutive pixels. A 12-wide register window
// (f[t-1], f[t], f[t+1] as float4s) covers all offsets d<=4 for all lanes;
// unconditional fmins are exact (every candidate f+d^2 >= true min).
// Rare tail (best > 25) falls back to bounded scalar search.
// ---------------------------------------------------------------------------
__global__ void k_row(void) {
    int t = blockIdx.x * blockDim.x + threadIdx.x;         // float4 index
    int px = t << 2;
    int col = px & (W - 1);                                // multiple of 4
    const float4* f4 = reinterpret_cast<const float4*>(g_f);

    float4 c = __ldg(f4 + t);
    float4 mm = (col >= 4)       ? __ldg(f4 + t - 1) : fg4();
    float4 pp = (col <= W - 8)   ? __ldg(f4 + t + 1) : fg4();

    float w[12] = {mm.x, mm.y, mm.z, mm.w, c.x, c.y, c.z, c.w, pp.x, pp.y, pp.z, pp.w};
    float best[4];
#pragma unroll
    for (int l = 0; l < 4; l++) best[l] = w[4 + l];
#pragma unroll
    for (int d = 1; d <= 4; d++) {
        float fd2 = (float)(d * d);
#pragma unroll
        for (int l = 0; l < 4; l++)
            best[l] = fminf(best[l], fminf(w[4 + l - d], w[4 + l + d]) + fd2);
    }
    // rare tail: only if best > 25 (next offset is d = 5)
#pragma unroll
    for (int l = 0; l < 4; l++) {
        if (best[l] > 25.0f) {
            int cl = col + l;
            int maxl = cl, maxr = (W - 1) - cl;
            for (int d = 5; d < W; d++) {
                float fd2 = (float)(d * d);
                if (fd2 >= best[l]) break;
                float lv = (d <= maxl) ? __ldg(&g_f[px + l - d]) : FG;
                float rv = (d <= maxr) ? __ldg(&g_f[px + l + d]) : FG;
                best[l] = fminf(best[l], fminf(lv, rv) + fd2);
            }
        }
    }

    float4 dv;
    dv.x = __fsqrt_rn(best[0]);
    dv.y = __fsqrt_rn(best[1]);
    dv.z = __fsqrt_rn(best[2]);
    dv.w = __fsqrt_rn(best[3]);
    reinterpret_cast<float4*>(g_d)[t] = dv;

    // block max (float bits preserve order for non-negative floats)
    float bm = fmaxf(fmaxf(dv.x, dv.y), fmaxf(dv.z, dv.w));
    unsigned int ib = __reduce_max_sync(0xffffffffu, __float_as_uint(bm));
    __shared__ unsigned int sm[TPB / 32];
    if ((threadIdx.x & 31) == 0) sm[threadIdx.x >> 5] = ib;
    __syncthreads();
    if (threadIdx.x == 0) {
        unsigned int m = sm[0];
#pragma unroll
        for (int wv = 1; wv < TPB / 32; wv++) m = max(m, sm[wv]);
        g_blockmax[blockIdx.x] = m;
    }
}

// ---------------------------------------------------------------------------
// K3: single-block reduction of the 4096 block maxima.
// ---------------------------------------------------------------------------
__global__ void k_reduce() {
    unsigned int v = 0u;
    for (int i = threadIdx.x; i < NB4; i += blockDim.x)
        v = max(v, g_blockmax[i]);
    v = __reduce_max_sync(0xffffffffu, v);
    __shared__ unsigned int sm[32];
    if ((threadIdx.x & 31) == 0) sm[threadIdx.x >> 5] = v;
    __syncthreads();
    if (threadIdx.x < 32) {
        unsigned int w = (threadIdx.x < (int)(blockDim.x >> 5)) ? sm[threadIdx.x] : 0u;
        w = __reduce_max_sync(0xffffffffu, w);
        if (threadIdx.x == 0) g_max_bits = w;
    }
}

// ---------------------------------------------------------------------------
// K4: normalize by global max, truncate toward zero (uint8 cast semantics;
// values in [0,255] so floorf). Harness exposes the output as float32.
// ---------------------------------------------------------------------------
__global__ void k_normalize(float* __restrict__ out) {
    int idx = blockIdx.x * blockDim.x + threadIdx.x;
    if (idx >= NPIX / 4) return;
    float m = __uint_as_float(g_max_bits);
    float4 v = reinterpret_cast<const float4*>(g_d)[idx];
    float4 r;
    if (m > 0.0f) {
        r.x = floorf(v.x / m * 255.0f);
        r.y = floorf(v.y / m * 255.0f);
        r.z = floorf(v.z / m * 255.0f);
        r.w = floorf(v.w / m * 255.0f);
    } else {
        r.x = floorf(v.x); r.y = floorf(v.y); r.z = floorf(v.z); r.w = floorf(v.w);
    }
    reinterpret_cast<float4*>(out)[idx] = r;
}

extern "C" void kernel_launch(void* const* d_in, const int* in_sizes, int n_in,
                              void* d_out, int out_size) {
    const float* img = (const float*)d_in[0];
    float* out = (float*)d_out;
    (void)in_sizes; (void)n_in; (void)out_size;

    k_colf<<<NB4, TPB>>>(img);
    k_row<<<NB4, TPB>>>();
    k_reduce<<<1, 1024>>>();
    k_normalize<<<(NPIX / 4 + 255) / 256, 256>>>(out);
}

// round 7
// speedup vs baseline: 2.3689x; 1.1306x over previous
#include <cuda_runtime.h>
#include <cstdint>

// Problem geometry (fixed by setup_inputs: 2048 x 2048 float32).
static constexpr int H = 2048;
static constexpr int W = 2048;
static constexpr int W4 = W / 4;           // float4s per row (512)
static constexpr int NPIX = H * W;
static constexpr int TPB = 256;
static constexpr int NB4 = NPIX / (TPB * 4);  // 4096 blocks (4 px / thread)
static constexpr float FG = 1.0e30f;       // "foreground / out of range" sentinel

// Scratch (device globals — no runtime allocation allowed).
__device__ float        g_f[NPIX];         // squared column distance
__device__ float        g_d[NPIX];         // distance (pre-normalize)
__device__ unsigned int g_blockmax[NB4];   // per-block max (float bits, >= 0)
__device__ float        g_scale;           // 255 / max  (1.0 if max == 0)

__device__ __forceinline__ float4 fg4() { return make_float4(FG, FG, FG, FG); }

// ---------------------------------------------------------------------------
// K1: f = (distance to nearest background along the column)^2.
// One thread = 4 consecutive pixels (one aligned float4). Probes k=1,2 are
// batched (4 independent loads -> MLP); remaining ks run the masked loop.
// ---------------------------------------------------------------------------
__global__ void k_colf(const float* __restrict__ img) {
    int t = blockIdx.x * blockDim.x + threadIdx.x;         // float4 index
    int row = (t << 2) >> 11;                              // W == 2048
    const float4* p = reinterpret_cast<const float4*>(img) + t;

    float4 v = __ldg(p);
    float f0 = (v.x <= 0.5f) ? 0.0f : FG;
    float f1 = (v.y <= 0.5f) ? 0.0f : FG;
    float f2 = (v.z <= 0.5f) ? 0.0f : FG;
    float f3 = (v.w <= 0.5f) ? 0.0f : FG;
    unsigned pend = (f0 != 0.0f ? 1u : 0u) | (f1 != 0.0f ? 2u : 0u) |
                    (f2 != 0.0f ? 4u : 0u) | (f3 != 0.0f ? 8u : 0u);
    if (pend) {
        int up = row, down = (H - 1) - row;
        // batched probes k = 1, 2 (independent loads)
        float4 a1 = (up   >= 1) ? __ldg(p - W4)     : fg4();
        float4 b1 = (down >= 1) ? __ldg(p + W4)     : fg4();
        float4 a2 = (up   >= 2) ? __ldg(p - 2 * W4) : fg4();
        float4 b2 = (down >= 2) ? __ldg(p + 2 * W4) : fg4();
        if ((pend & 1u) && (a1.x <= 0.5f || b1.x <= 0.5f)) { f0 = 1.0f; pend &= ~1u; }
        if ((pend & 2u) && (a1.y <= 0.5f || b1.y <= 0.5f)) { f1 = 1.0f; pend &= ~2u; }
        if ((pend & 4u) && (a1.z <= 0.5f || b1.z <= 0.5f)) { f2 = 1.0f; pend &= ~4u; }
        if ((pend & 8u) && (a1.w <= 0.5f || b1.w <= 0.5f)) { f3 = 1.0f; pend &= ~8u; }
        if ((pend & 1u) && (a2.x <= 0.5f || b2.x <= 0.5f)) { f0 = 4.0f; pend &= ~1u; }
        if ((pend & 2u) && (a2.y <= 0.5f || b2.y <= 0.5f)) { f1 = 4.0f; pend &= ~2u; }
        if ((pend & 4u) && (a2.z <= 0.5f || b2.z <= 0.5f)) { f2 = 4.0f; pend &= ~4u; }
        if ((pend & 8u) && (a2.w <= 0.5f || b2.w <= 0.5f)) { f3 = 4.0f; pend &= ~8u; }
        int kcap = max(up, down);
        for (int k = 3; k <= kcap && pend; k++) {
            float4 a = (k <= up)   ? __ldg(p - (size_t)k * W4) : fg4();
            float4 b = (k <= down) ? __ldg(p + (size_t)k * W4) : fg4();
            float fk2 = (float)(k * k);
            if ((pend & 1u) && (a.x <= 0.5f || b.x <= 0.5f)) { f0 = fk2; pend &= ~1u; }
            if ((pend & 2u) && (a.y <= 0.5f || b.y <= 0.5f)) { f1 = fk2; pend &= ~2u; }
            if ((pend & 4u) && (a.z <= 0.5f || b.z <= 0.5f)) { f2 = fk2; pend &= ~4u; }
            if ((pend & 8u) && (a.w <= 0.5f || b.w <= 0.5f)) { f3 = fk2; pend &= ~8u; }
        }
    }
    reinterpret_cast<float4*>(g_f)[t] = make_float4(f0, f1, f2, f3);
}

// ---------------------------------------------------------------------------
// K2: row pass. One thread = 4 consecutive pixels. A 12-wide register window
// (f[t-1], f[t], f[t+1] as float4s) covers all offsets d<=4 for all lanes;
// unconditional fmins are exact (every candidate f+d^2 >= true min).
// Rare tail (best > 25) falls back to bounded scalar search.
// ---------------------------------------------------------------------------
__global__ void k_row(void) {
    int t = blockIdx.x * blockDim.x + threadIdx.x;         // float4 index
    int px = t << 2;
    int col = px & (W - 1);                                // multiple of 4
    const float4* f4 = reinterpret_cast<const float4*>(g_f);

    float4 c = __ldg(f4 + t);
    float4 mm = (col >= 4)       ? __ldg(f4 + t - 1) : fg4();
    float4 pp = (col <= W - 8)   ? __ldg(f4 + t + 1) : fg4();

    float w[12] = {mm.x, mm.y, mm.z, mm.w, c.x, c.y, c.z, c.w, pp.x, pp.y, pp.z, pp.w};
    float best[4];
#pragma unroll
    for (int l = 0; l < 4; l++) best[l] = w[4 + l];
#pragma unroll
    for (int d = 1; d <= 4; d++) {
        float fd2 = (float)(d * d);
#pragma unroll
        for (int l = 0; l < 4; l++)
            best[l] = fminf(best[l], fminf(w[4 + l - d], w[4 + l + d]) + fd2);
    }
    // rare tail: only if best > 25 (next offset is d = 5)
#pragma unroll
    for (int l = 0; l < 4; l++) {
        if (best[l] > 25.0f) {
            int cl = col + l;
            int maxl = cl, maxr = (W - 1) - cl;
            for (int d = 5; d < W; d++) {
                float fd2 = (float)(d * d);
                if (fd2 >= best[l]) break;
                float lv = (d <= maxl) ? __ldg(&g_f[px + l - d]) : FG;
                float rv = (d <= maxr) ? __ldg(&g_f[px + l + d]) : FG;
                best[l] = fminf(best[l], fminf(lv, rv) + fd2);
            }
        }
    }

    float4 dv;
    dv.x = __fsqrt_rn(best[0]);
    dv.y = __fsqrt_rn(best[1]);
    dv.z = __fsqrt_rn(best[2]);
    dv.w = __fsqrt_rn(best[3]);
    reinterpret_cast<float4*>(g_d)[t] = dv;

    // block max (float bits preserve order for non-negative floats)
    float bm = fmaxf(fmaxf(dv.x, dv.y), fmaxf(dv.z, dv.w));
    unsigned int ib = __reduce_max_sync(0xffffffffu, __float_as_uint(bm));
    __shared__ unsigned int sm[TPB / 32];
    if ((threadIdx.x & 31) == 0) sm[threadIdx.x >> 5] = ib;
    __syncthreads();
    if (threadIdx.x == 0) {
        unsigned int m = sm[0];
#pragma unroll
        for (int wv = 1; wv < TPB / 32; wv++) m = max(m, sm[wv]);
        g_blockmax[blockIdx.x] = m;
    }
}

// ---------------------------------------------------------------------------
// K3: single-block reduction of the 4096 block maxima + precompute the
// normalization scale (one divide for the whole image).
// ---------------------------------------------------------------------------
__global__ void k_reduce() {
    unsigned int v = 0u;
    for (int i = threadIdx.x; i < NB4; i += blockDim.x)
        v = max(v, g_blockmax[i]);
    v = __reduce_max_sync(0xffffffffu, v);
    __shared__ unsigned int sm[32];
    if ((threadIdx.x & 31) == 0) sm[threadIdx.x >> 5] = v;
    __syncthreads();
    if (threadIdx.x < 32) {
        unsigned int w = (threadIdx.x < (int)(blockDim.x >> 5)) ? sm[threadIdx.x] : 0u;
        w = __reduce_max_sync(0xffffffffu, w);
        if (threadIdx.x == 0) {
            float m = __uint_as_float(w);
            g_scale = (m > 0.0f) ? (255.0f / m) : 1.0f;
        }
    }
}

// ---------------------------------------------------------------------------
// K4: normalize: one FMUL + floor per element (scale precomputed). Truncation
// toward zero == floor (values >= 0). Harness exposes output as float32.
// ---------------------------------------------------------------------------
__global__ void k_normalize(float* __restrict__ out) {
    int idx = blockIdx.x * blockDim.x + threadIdx.x;
    if (idx >= NPIX / 4) return;
    float s = g_scale;
    float4 v = reinterpret_cast<const float4*>(g_d)[idx];
    float4 r;
    r.x = floorf(v.x * s);
    r.y = floorf(v.y * s);
    r.z = floorf(v.z * s);
    r.w = floorf(v.w * s);
    reinterpret_cast<float4*>(out)[idx] = r;
}

extern "C" void kernel_launch(void* const* d_in, const int* in_sizes, int n_in,
                              void* d_out, int out_size) {
    const float* img = (const float*)d_in[0];
    float* out = (float*)d_out;
    (void)in_sizes; (void)n_in; (void)out_size;

    k_colf<<<NB4, TPB>>>(img);
    k_row<<<NB4, TPB>>>();
    k_reduce<<<1, 1024>>>();
    k_normalize<<<(NPIX / 4 + 255) / 256, 256>>>(out);
}

// round 8
// speedup vs baseline: 2.4243x; 1.0234x over previous
#include <cuda_runtime.h>
#include <cstdint>

// Problem geometry (fixed by setup_inputs: 2048 x 2048 float32).
static constexpr int H = 2048;
static constexpr int W = 2048;
static constexpr int W4 = W / 4;           // float4s per row (512)
static constexpr int NPIX = H * W;
static constexpr int TPB = 256;
static constexpr int NB4 = NPIX / (TPB * 4);  // 4096 blocks (4 px / thread)
static constexpr float FG = 1.0e30f;       // "foreground / out of range" sentinel

// Scratch (device globals — no runtime allocation allowed).
__device__ float        g_f[NPIX];         // squared column distance
__device__ float        g_d[NPIX];         // distance (pre-normalize)
__device__ unsigned int g_blockmax[NB4];   // per-block max (float bits, >= 0)
__device__ float        g_scale;           // 255 / max  (1.0 if max == 0)

__device__ __forceinline__ float4 fg4() { return make_float4(FG, FG, FG, FG); }

// ---------------------------------------------------------------------------
// K1: f = (distance to nearest background along the column)^2.
// One thread = 4 consecutive pixels (one aligned float4). Probes k=1,2 are
// batched (4 independent loads -> MLP); remaining ks run the masked loop.
// ---------------------------------------------------------------------------
__global__ void k_colf(const float* __restrict__ img) {
    int t = blockIdx.x * blockDim.x + threadIdx.x;         // float4 index
    int row = (t << 2) >> 11;                              // W == 2048
    const float4* p = reinterpret_cast<const float4*>(img) + t;

    float4 v = __ldg(p);
    float f0 = (v.x <= 0.5f) ? 0.0f : FG;
    float f1 = (v.y <= 0.5f) ? 0.0f : FG;
    float f2 = (v.z <= 0.5f) ? 0.0f : FG;
    float f3 = (v.w <= 0.5f) ? 0.0f : FG;
    unsigned pend = (f0 != 0.0f ? 1u : 0u) | (f1 != 0.0f ? 2u : 0u) |
                    (f2 != 0.0f ? 4u : 0u) | (f3 != 0.0f ? 8u : 0u);
    if (pend) {
        int up = row, down = (H - 1) - row;
        // batched probes k = 1, 2 (independent loads)
        float4 a1 = (up   >= 1) ? __ldg(p - W4)     : fg4();
        float4 b1 = (down >= 1) ? __ldg(p + W4)     : fg4();
        float4 a2 = (up   >= 2) ? __ldg(p - 2 * W4) : fg4();
        float4 b2 = (down >= 2) ? __ldg(p + 2 * W4) : fg4();
        if ((pend & 1u) && (a1.x <= 0.5f || b1.x <= 0.5f)) { f0 = 1.0f; pend &= ~1u; }
        if ((pend & 2u) && (a1.y <= 0.5f || b1.y <= 0.5f)) { f1 = 1.0f; pend &= ~2u; }
        if ((pend & 4u) && (a1.z <= 0.5f || b1.z <= 0.5f)) { f2 = 1.0f; pend &= ~4u; }
        if ((pend & 8u) && (a1.w <= 0.5f || b1.w <= 0.5f)) { f3 = 1.0f; pend &= ~8u; }
        if ((pend & 1u) && (a2.x <= 0.5f || b2.x <= 0.5f)) { f0 = 4.0f; pend &= ~1u; }
        if ((pend & 2u) && (a2.y <= 0.5f || b2.y <= 0.5f)) { f1 = 4.0f; pend &= ~2u; }
        if ((pend & 4u) && (a2.z <= 0.5f || b2.z <= 0.5f)) { f2 = 4.0f; pend &= ~4u; }
        if ((pend & 8u) && (a2.w <= 0.5f || b2.w <= 0.5f)) { f3 = 4.0f; pend &= ~8u; }
        int kcap = max(up, down);
        for (int k = 3; k <= kcap && pend; k++) {
            float4 a = (k <= up)   ? __ldg(p - (size_t)k * W4) : fg4();
            float4 b = (k <= down) ? __ldg(p + (size_t)k * W4) : fg4();
            float fk2 = (float)(k * k);
            if ((pend & 1u) && (a.x <= 0.5f || b.x <= 0.5f)) { f0 = fk2; pend &= ~1u; }
            if ((pend & 2u) && (a.y <= 0.5f || b.y <= 0.5f)) { f1 = fk2; pend &= ~2u; }
            if ((pend & 4u) && (a.z <= 0.5f || b.z <= 0.5f)) { f2 = fk2; pend &= ~4u; }
            if ((pend & 8u) && (a.w <= 0.5f || b.w <= 0.5f)) { f3 = fk2; pend &= ~8u; }
        }
    }
    reinterpret_cast<float4*>(g_f)[t] = make_float4(f0, f1, f2, f3);
}

// ---------------------------------------------------------------------------
// K2: row pass. One thread = 4 consecutive pixels. A 12-wide register window
// (f[t-1], f[t], f[t+1] as float4s) covers all offsets d<=4 for all lanes;
// unconditional fmins are exact (every candidate f+d^2 >= true min).
// Rare tail (best > 25) falls back to bounded scalar search.
// ---------------------------------------------------------------------------
__global__ void k_row(void) {
    int t = blockIdx.x * blockDim.x + threadIdx.x;         // float4 index
    int px = t << 2;
    int col = px & (W - 1);                                // multiple of 4
    const float4* f4 = reinterpret_cast<const float4*>(g_f);

    float4 c = __ldg(f4 + t);
    float4 mm = (col >= 4)       ? __ldg(f4 + t - 1) : fg4();
    float4 pp = (col <= W - 8)   ? __ldg(f4 + t + 1) : fg4();

    float w[12] = {mm.x, mm.y, mm.z, mm.w, c.x, c.y, c.z, c.w, pp.x, pp.y, pp.z, pp.w};
    float best[4];
#pragma unroll
    for (int l = 0; l < 4; l++) best[l] = w[4 + l];
#pragma unroll
    for (int d = 1; d <= 4; d++) {
        float fd2 = (float)(d * d);
#pragma unroll
        for (int l = 0; l < 4; l++)
            best[l] = fminf(best[l], fminf(w[4 + l - d], w[4 + l + d]) + fd2);
    }
    // rare tail: only if best > 25 (next offset is d = 5)
#pragma unroll
    for (int l = 0; l < 4; l++) {
        if (best[l] > 25.0f) {
            int cl = col + l;
            int maxl = cl, maxr = (W - 1) - cl;
            for (int d = 5; d < W; d++) {
                float fd2 = (float)(d * d);
                if (fd2 >= best[l]) break;
                float lv = (d <= maxl) ? __ldg(&g_f[px + l - d]) : FG;
                float rv = (d <= maxr) ? __ldg(&g_f[px + l + d]) : FG;
                best[l] = fminf(best[l], fminf(lv, rv) + fd2);
            }
        }
    }

    float4 dv;
    dv.x = __fsqrt_rn(best[0]);
    dv.y = __fsqrt_rn(best[1]);
    dv.z = __fsqrt_rn(best[2]);
    dv.w = __fsqrt_rn(best[3]);
    reinterpret_cast<float4*>(g_d)[t] = dv;

    // block max (float bits preserve order for non-negative floats)
    float bm = fmaxf(fmaxf(dv.x, dv.y), fmaxf(dv.z, dv.w));
    unsigned int ib = __reduce_max_sync(0xffffffffu, __float_as_uint(bm));
    __shared__ unsigned int sm[TPB / 32];
    if ((threadIdx.x & 31) == 0) sm[threadIdx.x >> 5] = ib;
    __syncthreads();
    if (threadIdx.x == 0) {
        unsigned int m = sm[0];
#pragma unroll
        for (int wv = 1; wv < TPB / 32; wv++) m = max(m, sm[wv]);
        g_blockmax[blockIdx.x] = m;
    }
}

// ---------------------------------------------------------------------------
// K3: single-block reduction of the 4096 block maxima + precompute the
// normalization scale (one divide for the whole image).
// ---------------------------------------------------------------------------
__global__ void k_reduce() {
    unsigned int v = 0u;
    for (int i = threadIdx.x; i < NB4; i += blockDim.x)
        v = max(v, g_blockmax[i]);
    v = __reduce_max_sync(0xffffffffu, v);
    __shared__ unsigned int sm[32];
    if ((threadIdx.x & 31) == 0) sm[threadIdx.x >> 5] = v;
    __syncthreads();
    if (threadIdx.x < 32) {
        unsigned int w = (threadIdx.x < (int)(blockDim.x >> 5)) ? sm[threadIdx.x] : 0u;
        w = __reduce_max_sync(0xffffffffu, w);
        if (threadIdx.x == 0) {
            float m = __uint_as_float(w);
            g_scale = (m > 0.0f) ? (255.0f / m) : 1.0f;
        }
    }
}

// ---------------------------------------------------------------------------
// K4: normalize: one FMUL + floor per element (scale precomputed). Each
// thread owns 4 float4s, loads batched back-to-back (MLP=4) to cover memory
// latency. Truncation toward zero == floor (values >= 0).
// ---------------------------------------------------------------------------
static constexpr int NORM_VPT = 4;                        // float4s per thread
static constexpr int NORM_TPB = 256;
static constexpr int NORM_NTHREADS = NPIX / 4 / NORM_VPT; // 262144
static constexpr int NORM_NBLK = NORM_NTHREADS / NORM_TPB;

__global__ void k_normalize(float* __restrict__ out) {
    int base = blockIdx.x * blockDim.x + threadIdx.x;
    int stride = NORM_NTHREADS;                           // grid-wide stride
    float s = g_scale;
    const float4* dp = reinterpret_cast<const float4*>(g_d);
    float4* op = reinterpret_cast<float4*>(out);

    float4 v[NORM_VPT];
#pragma unroll
    for (int i = 0; i < NORM_VPT; i++)                    // batched loads (MLP)
        v[i] = __ldg(dp + base + i * stride);
#pragma unroll
    for (int i = 0; i < NORM_VPT; i++) {
        float4 r;
        r.x = floorf(v[i].x * s);
        r.y = floorf(v[i].y * s);
        r.z = floorf(v[i].z * s);
        r.w = floorf(v[i].w * s);
        op[base + i * stride] = r;
    }
}

extern "C" void kernel_launch(void* const* d_in, const int* in_sizes, int n_in,
                              void* d_out, int out_size) {
    const float* img = (const float*)d_in[0];
    float* out = (float*)d_out;
    (void)in_sizes; (void)n_in; (void)out_size;

    k_colf<<<NB4, TPB>>>(img);
    k_row<<<NB4, TPB>>>();
    k_reduce<<<1, 1024>>>();
    k_normalize<<<NORM_NBLK, NORM_TPB>>>(out);
}